// round 5
// baseline (speedup 1.0000x reference)
#include <cuda_runtime.h>
#include <cuda_bf16.h>
#include <math.h>

// Problem dims
#define BB 8
#define SS 512
#define DD 1024
#define HH 1024   // HID
#define NHH 16
#define CC 64
#define MT (BB*SS)          // 4096 tokens
#define NBATCH (BB*NHH)     // 128 attention batches

// ---------------- scratch (device globals; no runtime allocation) ----------------
__device__ float g_q [MT*HH];
__device__ float g_k [MT*HH];
__device__ float g_v [MT*HH];
__device__ float g_a [MT*HH];
__device__ float g_t [MT*HH];
__device__ float g_x1[MT*DD];
__device__ float g_x2[MT*DD];
__device__ float g_sc[(size_t)NBATCH*SS*SS]; // 134 MB scores scratch

// ---------------- generic batched SGEMM, double-buffered ----------------
// C = alpha * A @ B (+ bias[n]),  A:[M,K] row-major lda, B:[K,N] (or [N,K] if TB) ldb
// two-level batch: z -> (outer = z/nInner, inner = z%nInner) with per-operand strides.
template<int BM,int BN,int BK,int TM,int TN,bool TB>
__global__ __launch_bounds__((BM/TM)*(BN/TN))
void gemm_kernel(int M,int N,int K,
                 const float* __restrict__ A, int lda, long long sAo, long long sAi,
                 const float* __restrict__ Bp, int ldb, long long sBo, long long sBi,
                 float* __restrict__ Cp, int ldc, long long sCo, long long sCi,
                 const float* __restrict__ bias, float alpha, int nInner)
{
    constexpr int NT = (BM/TM)*(BN/TN);
    constexpr int LA = (BM*BK)/(4*NT);   // float4 prefetch regs per thread (A)
    constexpr int LB = (BK*BN)/(4*NT);   // float4 prefetch regs per thread (B)
    static_assert(LA >= 1 && LB >= 1, "tile too small for thread count");

    __shared__ __align__(16) float As[2][BK*BM];
    __shared__ __align__(16) float Bs[2][BK*BN];

    int z = blockIdx.z;
    int oz = z / nInner, iz = z % nInner;
    A  += oz*sAo + iz*sAi;
    Bp += oz*sBo + iz*sBi;
    Cp += oz*sCo + iz*sCi;

    const int m0 = blockIdx.y*BM, n0 = blockIdx.x*BN;
    const int tid = threadIdx.x;
    const int tx = tid % (BN/TN), ty = tid / (BN/TN);

    float4 ra[LA], rb[LB];

    // ---- loaders: global -> regs ----
    auto loadA = [&](int k0) {
#pragma unroll
        for (int l=0;l<LA;l++) {
            int idx = tid + l*NT;
            int m   = idx / (BK/4);
            int k4  = (idx % (BK/4))*4;
            ra[l] = *(const float4*)(A + (size_t)(m0+m)*lda + k0 + k4);
        }
    };
    auto loadB = [&](int k0) {
        if (!TB) {
#pragma unroll
            for (int l=0;l<LB;l++) {
                int idx = tid + l*NT;
                int k   = idx / (BN/4);
                int n4  = (idx % (BN/4))*4;
                rb[l] = *(const float4*)(Bp + (size_t)(k0+k)*ldb + n0 + n4);
            }
        } else {
#pragma unroll
            for (int l=0;l<LB;l++) {
                int idx = tid + l*NT;
                int n   = idx / (BK/4);
                int k4  = (idx % (BK/4))*4;
                rb[l] = *(const float4*)(Bp + (size_t)(n0+n)*ldb + k0 + k4);
            }
        }
    };
    // ---- stores: regs -> smem (A transposed: As[k][m]) ----
    auto storeA = [&](int buf) {
#pragma unroll
        for (int l=0;l<LA;l++) {
            int idx = tid + l*NT;
            int m   = idx / (BK/4);
            int k4  = (idx % (BK/4))*4;
            As[buf][(k4+0)*BM+m]=ra[l].x; As[buf][(k4+1)*BM+m]=ra[l].y;
            As[buf][(k4+2)*BM+m]=ra[l].z; As[buf][(k4+3)*BM+m]=ra[l].w;
        }
    };
    auto storeB = [&](int buf) {
        if (!TB) {
#pragma unroll
            for (int l=0;l<LB;l++) {
                int idx = tid + l*NT;
                int k   = idx / (BN/4);
                int n4  = (idx % (BN/4))*4;
                *(float4*)(&Bs[buf][k*BN + n4]) = rb[l];
            }
        } else {
#pragma unroll
            for (int l=0;l<LB;l++) {
                int idx = tid + l*NT;
                int n   = idx / (BK/4);
                int k4  = (idx % (BK/4))*4;
                Bs[buf][(k4+0)*BN+n]=rb[l].x; Bs[buf][(k4+1)*BN+n]=rb[l].y;
                Bs[buf][(k4+2)*BN+n]=rb[l].z; Bs[buf][(k4+3)*BN+n]=rb[l].w;
            }
        }
    };

    float acc[TM][TN];
#pragma unroll
    for (int i=0;i<TM;i++)
#pragma unroll
        for (int j=0;j<TN;j++) acc[i][j]=0.f;

    // prologue: tile 0 into buffer 0
    loadA(0); loadB(0);
    storeA(0); storeB(0);
    __syncthreads();

    int buf = 0;
    for (int k0=0;k0<K;k0+=BK) {
        const bool has_next = (k0 + BK) < K;
        if (has_next) { loadA(k0+BK); loadB(k0+BK); }  // prefetch overlaps compute

#pragma unroll
        for (int k=0;k<BK;k++) {
            float a[TM], b[TN];
            const float* Ak = &As[buf][k*BM + ty*TM];
            const float* Bk = &Bs[buf][k*BN + tx*TN];
#pragma unroll
            for (int i=0;i<TM/4;i++) { float4 v=*(const float4*)(Ak+i*4);
                a[i*4+0]=v.x; a[i*4+1]=v.y; a[i*4+2]=v.z; a[i*4+3]=v.w; }
#pragma unroll
            for (int j=0;j<TN/4;j++) { float4 v=*(const float4*)(Bk+j*4);
                b[j*4+0]=v.x; b[j*4+1]=v.y; b[j*4+2]=v.z; b[j*4+3]=v.w; }
#pragma unroll
            for (int i=0;i<TM;i++)
#pragma unroll
                for (int j=0;j<TN;j++) acc[i][j] = fmaf(a[i], b[j], acc[i][j]);
        }

        if (has_next) {
            storeA(buf^1); storeB(buf^1);
            __syncthreads();
            buf ^= 1;
        }
    }

    // epilogue
#pragma unroll
    for (int i=0;i<TM;i++) {
        size_t m = (size_t)(m0 + ty*TM + i);
#pragma unroll
        for (int j4=0;j4<TN/4;j4++) {
            int n = n0 + tx*TN + j4*4;
            float4 v;
            v.x = acc[i][j4*4+0]*alpha; v.y = acc[i][j4*4+1]*alpha;
            v.z = acc[i][j4*4+2]*alpha; v.w = acc[i][j4*4+3]*alpha;
            if (bias) { v.x+=bias[n]; v.y+=bias[n+1]; v.z+=bias[n+2]; v.w+=bias[n+3]; }
            *(float4*)(Cp + m*ldc + n) = v;
        }
    }
}

// ---------------- channel self-attention core ----------------
// per (b,s): 16 heads x 64 channels. aff[q,k] = (Q[q]/8)*K[k], causal over channels,
// softmax over k, out[q] = sum_k p[q,k]*V[k].
__global__ __launch_bounds__(1024)
void self_attn_kernel(const float* __restrict__ Q, const float* __restrict__ Kx,
                      const float* __restrict__ V, float* __restrict__ O)
{
    __shared__ float qs[1024], ks[1024], vs[1024];
    size_t base = (size_t)blockIdx.x*1024;
    int tid = threadIdx.x;
    qs[tid] = Q[base+tid]*0.125f;
    ks[tid] = Kx[base+tid];
    vs[tid] = V[base+tid];
    __syncthreads();
    int q = tid & 63, hb = tid & ~63;
    float qv = qs[hb+q];
    float m = -1e30f;
    for (int k=0;k<=q;k++) m = fmaxf(m, qv*ks[hb+k]);
    float s=0.f, a=0.f;
    for (int k=0;k<=q;k++) {
        float e = __expf(qv*ks[hb+k]-m);
        s += e; a = fmaf(e, vs[hb+k], a);
    }
    O[base+tid] = a/s;
}

// ---------------- softmax over rows of 512 (warp per row) ----------------
__global__ __launch_bounds__(256)
void softmax512_kernel(float* __restrict__ P)
{
    int row  = blockIdx.x*8 + (threadIdx.x>>5);
    int lane = threadIdx.x & 31;
    float* r = P + (size_t)row*512;
    float v[16];
    float m = -1e30f;
#pragma unroll
    for (int i=0;i<16;i++) { v[i] = r[lane + i*32]; m = fmaxf(m, v[i]); }
#pragma unroll
    for (int o=16;o;o>>=1) m = fmaxf(m, __shfl_xor_sync(0xffffffffu, m, o));
    float s = 0.f;
#pragma unroll
    for (int i=0;i<16;i++) { v[i] = __expf(v[i]-m); s += v[i]; }
#pragma unroll
    for (int o=16;o;o>>=1) s += __shfl_xor_sync(0xffffffffu, s, o);
    float inv = 1.f/s;
#pragma unroll
    for (int i=0;i<16;i++) r[lane + i*32] = v[i]*inv;
}

// ---------------- residual add + LayerNorm (block per row of 1024) ----------------
__global__ __launch_bounds__(256)
void add_ln_kernel(const float* __restrict__ a, const float* __restrict__ b,
                   const float* __restrict__ gamma, const float* __restrict__ beta,
                   float* __restrict__ out)
{
    __shared__ float s[1024];
    __shared__ float red[33];
    size_t base = (size_t)blockIdx.x*1024;
    int tid = threadIdx.x;
    float local = 0.f;
#pragma unroll
    for (int i=0;i<4;i++) {
        int idx = tid + i*256;
        float v = a[base+idx] + b[base+idx];
        s[idx] = v; local += v;
    }
    // block reduce sum
    int lane = tid & 31, w = tid >> 5;
#pragma unroll
    for (int o=16;o;o>>=1) local += __shfl_xor_sync(0xffffffffu, local, o);
    if (lane==0) red[w] = local;
    __syncthreads();
    if (w==0) {
        float t = (lane<8)? red[lane] : 0.f;
#pragma unroll
        for (int o=16;o;o>>=1) t += __shfl_xor_sync(0xffffffffu, t, o);
        if (lane==0) red[32] = t * (1.f/1024.f);
    }
    __syncthreads();
    float mu = red[32];
    __syncthreads();
    float lv = 0.f;
#pragma unroll
    for (int i=0;i<4;i++) { float d = s[tid+i*256]-mu; lv = fmaf(d,d,lv); }
#pragma unroll
    for (int o=16;o;o>>=1) lv += __shfl_xor_sync(0xffffffffu, lv, o);
    if (lane==0) red[w] = lv;
    __syncthreads();
    if (w==0) {
        float t = (lane<8)? red[lane] : 0.f;
#pragma unroll
        for (int o=16;o;o>>=1) t += __shfl_xor_sync(0xffffffffu, t, o);
        if (lane==0) red[32] = rsqrtf(t*(1.f/1024.f) + 1e-5f);
    }
    __syncthreads();
    float rstd = red[32];
#pragma unroll
    for (int i=0;i<4;i++) {
        int idx = tid + i*256;
        out[base+idx] = (s[idx]-mu)*rstd*gamma[idx] + beta[idx];
    }
}

// ---------------- launch ----------------
static void launch_gemm_big(const float* A, const float* W, const float* bias, float* C)
{
    dim3 g(HH/128, MT/128, 1);
    gemm_kernel<128,128,16,8,8,false><<<g,256>>>(MT,HH,DD,
        A,DD,0,0,  W,HH,0,0,  C,HH,0,0,  bias, 1.f, 1);
}

extern "C" void kernel_launch(void* const* d_in, const int* in_sizes, int n_in,
                              void* d_out, int out_size)
{
    const float* x    = (const float*)d_in[0];
    const float* h    = (const float*)d_in[1];
    const float* Wq   = (const float*)d_in[2];
    const float* bq   = (const float*)d_in[3];
    const float* Wk   = (const float*)d_in[4];
    const float* bk   = (const float*)d_in[5];
    const float* Wv   = (const float*)d_in[6];
    const float* bv   = (const float*)d_in[7];
    const float* Wo   = (const float*)d_in[8];
    const float* bo   = (const float*)d_in[9];
    const float* Wcq  = (const float*)d_in[10];
    const float* bcq  = (const float*)d_in[11];
    const float* Wck  = (const float*)d_in[12];
    const float* bck  = (const float*)d_in[13];
    const float* Wcv  = (const float*)d_in[14];
    const float* bcv  = (const float*)d_in[15];
    const float* Wco  = (const float*)d_in[16];
    const float* bco  = (const float*)d_in[17];
    const float* gamma= (const float*)d_in[18];
    const float* beta = (const float*)d_in[19];
    const float* W1   = (const float*)d_in[20];
    const float* b1   = (const float*)d_in[21];
    const float* W2   = (const float*)d_in[22];
    const float* b2   = (const float*)d_in[23];
    float* out = (float*)d_out;

    // resolve scratch addresses once (legal during capture: not stream ops)
    static float *q=nullptr,*k,*v,*a,*t,*x1,*x2,*sc;
    if (!q) {
        cudaGetSymbolAddress((void**)&q,  g_q);
        cudaGetSymbolAddress((void**)&k,  g_k);
        cudaGetSymbolAddress((void**)&v,  g_v);
        cudaGetSymbolAddress((void**)&a,  g_a);
        cudaGetSymbolAddress((void**)&t,  g_t);
        cudaGetSymbolAddress((void**)&x1, g_x1);
        cudaGetSymbolAddress((void**)&x2, g_x2);
        cudaGetSymbolAddress((void**)&sc, g_sc);
    }

    const long long sT = (long long)SS*HH;        // token-batch stride (per b)
    const long long sH = 64;                      // head stride inside HID
    const long long sSo = (long long)NHH*SS*SS;   // scores: per-b stride
    const long long sSi = (long long)SS*SS;       // scores: per-h stride

    // ---- self attention ----
    launch_gemm_big(x, Wq, bq, q);
    launch_gemm_big(x, Wk, bk, k);
    launch_gemm_big(x, Wv, bv, v);
    self_attn_kernel<<<MT, 1024>>>(q, k, v, a);
    launch_gemm_big(a, Wo, bo, t);
    add_ln_kernel<<<MT, 256>>>(t, x, gamma, beta, x1);

    // ---- cross attention ----
    launch_gemm_big(x1, Wcq, bcq, q);
    launch_gemm_big(h,  Wck, bck, k);
    launch_gemm_big(h,  Wcv, bcv, v);
    {   // scores = Q K^T / 32   (batched over B x NH)
        dim3 g(SS/64, SS/64, NBATCH);
        gemm_kernel<64,64,16,4,4,true><<<g,256>>>(SS,SS,CC,
            q, HH, sT, sH,
            k, HH, sT, sH,
            sc, SS, sSo, sSi,
            nullptr, 1.f/32.f, NHH);
    }
    softmax512_kernel<<<(NBATCH*SS)/8, 256>>>(sc);
    {   // O = P V  (writes directly into [B,S,HID] layout)
        dim3 g(CC/64, SS/64, NBATCH);
        gemm_kernel<64,64,16,4,4,false><<<g,256>>>(SS,CC,SS,
            sc, SS, sSo, sSi,
            v,  HH, sT, sH,
            a,  HH, sT, sH,
            nullptr, 1.f, NHH);
    }
    launch_gemm_big(a, Wco, bco, t);
    add_ln_kernel<<<MT, 256>>>(t, x1, gamma, beta, x2);

    // ---- FFN (linear-linear) ----
    launch_gemm_big(x2, W1, b1, q);
    launch_gemm_big(q,  W2, b2, t);
    add_ln_kernel<<<MT, 256>>>(t, x2, gamma, beta, out);
}

// round 11
// speedup vs baseline: 1.9164x; 1.9164x over previous
#include <cuda_runtime.h>
#include <cuda_bf16.h>
#include <math.h>
#include <stdint.h>

// Problem dims
#define BB 8
#define SS 512
#define DD 1024
#define HH 1024   // HID
#define NHH 16
#define CC 64
#define MT (BB*SS)          // 4096 tokens
#define NBATCH (BB*NHH)     // 128 attention batches

// ---------------- scratch (device globals; no runtime allocation) ----------------
__device__ float g_q [MT*HH];
__device__ float g_k [MT*HH];
__device__ float g_v [MT*HH];
__device__ float g_a [MT*HH];
__device__ float g_t [MT*HH];
__device__ float g_x1[MT*DD];
__device__ float g_x2[MT*DD];
__device__ float g_sc[(size_t)NBATCH*SS*SS]; // 134 MB scores scratch
// bf16 split planes
__device__ __nv_bfloat16 g_ah[MT*DD];
__device__ __nv_bfloat16 g_al[MT*DD];
__device__ __nv_bfloat16 g_wh[DD*HH];
__device__ __nv_bfloat16 g_wl[DD*HH];

// ================= portable tensor-op helpers (sm_80+ PTX, works on compute_103) =================
__device__ __forceinline__ uint32_t smem_u32(const void* p) {
    uint32_t a;
    asm("{ .reg .u64 t; cvta.to.shared.u64 t, %1; cvt.u32.u64 %0, t; }" : "=r"(a) : "l"(p));
    return a;
}
#define CP_ASYNC16(sm, g) \
    asm volatile("cp.async.cg.shared.global [%0], [%1], 16;" :: "r"(sm), "l"(g) : "memory")
#define CP_COMMIT() asm volatile("cp.async.commit_group;" ::: "memory")
#define CP_WAIT1()  asm volatile("cp.async.wait_group 1;" ::: "memory")
#define CP_WAIT0()  asm volatile("cp.async.wait_group 0;" ::: "memory")

__device__ __forceinline__ void ldsm4(uint32_t& r0, uint32_t& r1, uint32_t& r2, uint32_t& r3,
                                      uint32_t addr) {
    asm volatile("ldmatrix.sync.aligned.m8n8.x4.shared.b16 {%0,%1,%2,%3}, [%4];"
        : "=r"(r0), "=r"(r1), "=r"(r2), "=r"(r3) : "r"(addr));
}
__device__ __forceinline__ void mma_bf16(float* d, const uint32_t* a, const uint32_t* b) {
    asm volatile(
        "mma.sync.aligned.m16n8k16.row.col.f32.bf16.bf16.f32 "
        "{%0,%1,%2,%3},{%4,%5,%6,%7},{%8,%9},{%0,%1,%2,%3};"
        : "+f"(d[0]), "+f"(d[1]), "+f"(d[2]), "+f"(d[3])
        : "r"(a[0]), "r"(a[1]), "r"(a[2]), "r"(a[3]), "r"(b[0]), "r"(b[1]));
}

// ================= tensor GEMM: C[M,N] = (Ah+Al) @ (Bh+Bl)^T + bias =================
// A planes [M,K] bf16 row-major; B planes [N,K] bf16 row-major (pre-transposed W).
// M=4096, N=1024, K=1024; tile 128x128, BK=64, 2-stage cp.async pipeline.
// smem layout per stage: 4 planes (Ah,Al,Bh,Bl), each 128 rows x 8 chunks of 16B,
// chunk swizzle: ch ^ (row&7).
#define MM_PLANE 16384
#define MM_STAGE (4*MM_PLANE)     // 64 KB
#define MM_SMEM  (2*MM_STAGE)     // 128 KB

__global__ __launch_bounds__(256)
void tgemm_kernel(const __nv_bfloat16* __restrict__ Ah, const __nv_bfloat16* __restrict__ Al,
                  const __nv_bfloat16* __restrict__ Bh, const __nv_bfloat16* __restrict__ Bl,
                  const float* __restrict__ bias, float* __restrict__ C)
{
    extern __shared__ char smem[];
    const int K = DD, N = HH;
    const int tid = threadIdx.x, wid = tid >> 5, lane = tid & 31;
    const int m0 = blockIdx.y * 128, n0 = blockIdx.x * 128;
    const int wr = wid >> 2, wc = wid & 3;    // warp tile: rows wr*64, cols wc*32
    uint32_t sb = smem_u32(smem);

    const __nv_bfloat16* srcs[4] = {Ah, Al, Bh, Bl};

    // stage chunk c (K-cols [c*64, c*64+64)) into buffer s
    auto stage = [&](int s, int c) {
#pragma unroll
        for (int p = 0; p < 4; p++) {
            int rbase = (p < 2) ? m0 : n0;
#pragma unroll
            for (int l = 0; l < 4; l++) {
                int idx = tid + l * 256;           // 1024 chunks per plane
                int row = idx >> 3, ch = idx & 7;
                const __nv_bfloat16* g = srcs[p] + (size_t)(rbase + row) * K + c * 64 + ch * 8;
                uint32_t sm = sb + s * MM_STAGE + p * MM_PLANE
                            + (row * 8 + (ch ^ (row & 7))) * 16;
                CP_ASYNC16(sm, g);
            }
        }
    };

    float acc[4][4][4];
#pragma unroll
    for (int i = 0; i < 4; i++)
#pragma unroll
        for (int j = 0; j < 4; j++)
#pragma unroll
            for (int r = 0; r < 4; r++) acc[i][j][r] = 0.f;

    stage(0, 0); CP_COMMIT();
    stage(1, 1); CP_COMMIT();

    const int NCH = K / 64;    // 16
    for (int c = 0; c < NCH; c++) {
        if (c == NCH - 1) { CP_WAIT0(); } else { CP_WAIT1(); }
        __syncthreads();
        uint32_t base = sb + (c & 1) * MM_STAGE;

#pragma unroll
        for (int j = 0; j < 4; j++) {       // 4 k16 steps within 64-chunk
            // B fragments: 4 n8 tiles (cols wc*32 + bt*8), hi + lo planes
            uint32_t bh[4][2], bl[4][2];
#pragma unroll
            for (int n2 = 0; n2 < 2; n2++) {   // each x4 covers 16 n-rows -> 2 frags
                int nrow = wc * 32 + n2 * 16 + (lane & 15);
                int ch = 2 * j + (lane >> 4);
                uint32_t off = (nrow * 8 + (ch ^ (nrow & 7))) * 16;
                uint32_t r0, r1, r2, r3;
                ldsm4(r0, r1, r2, r3, base + 2 * MM_PLANE + off);   // Bh
                bh[n2*2][0] = r0; bh[n2*2][1] = r2;
                bh[n2*2+1][0] = r1; bh[n2*2+1][1] = r3;
                ldsm4(r0, r1, r2, r3, base + 3 * MM_PLANE + off);   // Bl
                bl[n2*2][0] = r0; bl[n2*2][1] = r2;
                bl[n2*2+1][0] = r1; bl[n2*2+1][1] = r3;
            }
#pragma unroll
            for (int at = 0; at < 4; at++) {   // 4 m16 tiles (rows wr*64 + at*16)
                int arow = wr * 64 + at * 16 + (lane & 15);
                int ch = 2 * j + (lane >> 4);
                uint32_t off = (arow * 8 + (ch ^ (arow & 7))) * 16;
                uint32_t ah[4], al[4];
                ldsm4(ah[0], ah[1], ah[2], ah[3], base + 0 * MM_PLANE + off);
                ldsm4(al[0], al[1], al[2], al[3], base + 1 * MM_PLANE + off);
#pragma unroll
                for (int bt = 0; bt < 4; bt++) {
                    mma_bf16(acc[at][bt], ah, bh[bt]);
                    mma_bf16(acc[at][bt], ah, bl[bt]);
                    mma_bf16(acc[at][bt], al, bh[bt]);
                }
            }
        }
        __syncthreads();
        if (c + 2 < NCH) { stage(c & 1, c + 2); CP_COMMIT(); }
    }

    // epilogue: fp32 accum + bias -> C
#pragma unroll
    for (int at = 0; at < 4; at++) {
        int r0 = m0 + wr * 64 + at * 16 + (lane >> 2);
#pragma unroll
        for (int bt = 0; bt < 4; bt++) {
            int col = n0 + wc * 32 + bt * 8 + (lane & 3) * 2;
            float b0 = bias[col], b1 = bias[col + 1];
            float2 v0 = make_float2(acc[at][bt][0] + b0, acc[at][bt][1] + b1);
            float2 v1 = make_float2(acc[at][bt][2] + b0, acc[at][bt][3] + b1);
            *(float2*)(C + (size_t)r0 * N + col) = v0;
            *(float2*)(C + (size_t)(r0 + 8) * N + col) = v1;
        }
    }
}

// ================= split conversions =================
// fp32 -> (hi, lo) bf16 planes, elementwise
__global__ __launch_bounds__(256)
void actsplit_kernel(const float* __restrict__ x, __nv_bfloat16* __restrict__ hi,
                     __nv_bfloat16* __restrict__ lo)
{
    int i = blockIdx.x * 256 + threadIdx.x;   // one float4 per thread
    float4 v = ((const float4*)x)[i];
    __nv_bfloat16 h0=__float2bfloat16(v.x), h1=__float2bfloat16(v.y),
                  h2=__float2bfloat16(v.z), h3=__float2bfloat16(v.w);
    __nv_bfloat16 l0=__float2bfloat16(v.x-__bfloat162float(h0)),
                  l1=__float2bfloat16(v.y-__bfloat162float(h1)),
                  l2=__float2bfloat16(v.z-__bfloat162float(h2)),
                  l3=__float2bfloat16(v.w-__bfloat162float(h3));
    __nv_bfloat16 hb[4]={h0,h1,h2,h3}, lb[4]={l0,l1,l2,l3};
    *(uint2*)(hi + 4*(size_t)i) = *(uint2*)hb;
    *(uint2*)(lo + 4*(size_t)i) = *(uint2*)lb;
}

// W[K,N] fp32 -> transposed planes [N,K] bf16 (32x32 smem transpose)
__global__ __launch_bounds__(256)
void wsplit_kernel(const float* __restrict__ W, __nv_bfloat16* __restrict__ th,
                   __nv_bfloat16* __restrict__ tl)
{
    __shared__ float t[32][33];
    const int Kd = DD, Nd = HH;
    int n0 = blockIdx.x * 32, k0 = blockIdx.y * 32;
    int tx = threadIdx.x & 31, ty = threadIdx.x >> 5;   // 32x8
    for (int i = ty; i < 32; i += 8)
        t[i][tx] = W[(size_t)(k0 + i) * Nd + n0 + tx];
    __syncthreads();
    for (int i = ty; i < 32; i += 8) {
        float v = t[tx][i];                              // W[k0+tx][n0+i]
        __nv_bfloat16 h = __float2bfloat16(v);
        th[(size_t)(n0 + i) * Kd + k0 + tx] = h;
        tl[(size_t)(n0 + i) * Kd + k0 + tx] = __float2bfloat16(v - __bfloat162float(h));
    }
}

// ---------------- SIMT batched GEMM (cross-attn only), double-buffered ----------------
template<int BM,int BN,int BK,int TM,int TN,bool TB>
__global__ __launch_bounds__((BM/TM)*(BN/TN))
void gemm_kernel(int M,int N,int K,
                 const float* __restrict__ A, int lda, long long sAo, long long sAi,
                 const float* __restrict__ Bp, int ldb, long long sBo, long long sBi,
                 float* __restrict__ Cp, int ldc, long long sCo, long long sCi,
                 const float* __restrict__ bias, float alpha, int nInner)
{
    constexpr int NT = (BM/TM)*(BN/TN);
    constexpr int LA = (BM*BK)/(4*NT);
    constexpr int LB = (BK*BN)/(4*NT);
    static_assert(LA >= 1 && LB >= 1, "tile too small");

    __shared__ __align__(16) float As[2][BK*BM];
    __shared__ __align__(16) float Bs[2][BK*BN];

    int z = blockIdx.z;
    int oz = z / nInner, iz = z % nInner;
    A  += oz*sAo + iz*sAi;
    Bp += oz*sBo + iz*sBi;
    Cp += oz*sCo + iz*sCi;

    const int m0 = blockIdx.y*BM, n0 = blockIdx.x*BN;
    const int tid = threadIdx.x;
    const int tx = tid % (BN/TN), ty = tid / (BN/TN);

    float4 ra[LA], rb[LB];
    auto loadA = [&](int k0) {
#pragma unroll
        for (int l=0;l<LA;l++) {
            int idx = tid + l*NT;
            int m  = idx / (BK/4);
            int k4 = (idx % (BK/4))*4;
            ra[l] = *(const float4*)(A + (size_t)(m0+m)*lda + k0 + k4);
        }
    };
    auto loadB = [&](int k0) {
        if (!TB) {
#pragma unroll
            for (int l=0;l<LB;l++) {
                int idx = tid + l*NT;
                int k  = idx / (BN/4);
                int n4 = (idx % (BN/4))*4;
                rb[l] = *(const float4*)(Bp + (size_t)(k0+k)*ldb + n0 + n4);
            }
        } else {
#pragma unroll
            for (int l=0;l<LB;l++) {
                int idx = tid + l*NT;
                int n  = idx / (BK/4);
                int k4 = (idx % (BK/4))*4;
                rb[l] = *(const float4*)(Bp + (size_t)(n0+n)*ldb + k0 + k4);
            }
        }
    };
    auto storeA = [&](int buf) {
#pragma unroll
        for (int l=0;l<LA;l++) {
            int idx = tid + l*NT;
            int m  = idx / (BK/4);
            int k4 = (idx % (BK/4))*4;
            As[buf][(k4+0)*BM+m]=ra[l].x; As[buf][(k4+1)*BM+m]=ra[l].y;
            As[buf][(k4+2)*BM+m]=ra[l].z; As[buf][(k4+3)*BM+m]=ra[l].w;
        }
    };
    auto storeB = [&](int buf) {
        if (!TB) {
#pragma unroll
            for (int l=0;l<LB;l++) {
                int idx = tid + l*NT;
                int k  = idx / (BN/4);
                int n4 = (idx % (BN/4))*4;
                *(float4*)(&Bs[buf][k*BN + n4]) = rb[l];
            }
        } else {
#pragma unroll
            for (int l=0;l<LB;l++) {
                int idx = tid + l*NT;
                int n  = idx / (BK/4);
                int k4 = (idx % (BK/4))*4;
                Bs[buf][(k4+0)*BN+n]=rb[l].x; Bs[buf][(k4+1)*BN+n]=rb[l].y;
                Bs[buf][(k4+2)*BN+n]=rb[l].z; Bs[buf][(k4+3)*BN+n]=rb[l].w;
            }
        }
    };

    float acc[TM][TN];
#pragma unroll
    for (int i=0;i<TM;i++)
#pragma unroll
        for (int j=0;j<TN;j++) acc[i][j]=0.f;

    loadA(0); loadB(0);
    storeA(0); storeB(0);
    __syncthreads();

    int buf = 0;
    for (int k0=0;k0<K;k0+=BK) {
        const bool has_next = (k0 + BK) < K;
        if (has_next) { loadA(k0+BK); loadB(k0+BK); }
#pragma unroll
        for (int k=0;k<BK;k++) {
            float a[TM], b[TN];
            const float* Ak = &As[buf][k*BM + ty*TM];
            const float* Bk = &Bs[buf][k*BN + tx*TN];
#pragma unroll
            for (int i=0;i<TM/4;i++) { float4 v=*(const float4*)(Ak+i*4);
                a[i*4+0]=v.x; a[i*4+1]=v.y; a[i*4+2]=v.z; a[i*4+3]=v.w; }
#pragma unroll
            for (int j=0;j<TN/4;j++) { float4 v=*(const float4*)(Bk+j*4);
                b[j*4+0]=v.x; b[j*4+1]=v.y; b[j*4+2]=v.z; b[j*4+3]=v.w; }
#pragma unroll
            for (int i=0;i<TM;i++)
#pragma unroll
                for (int j=0;j<TN;j++) acc[i][j] = fmaf(a[i], b[j], acc[i][j]);
        }
        if (has_next) {
            storeA(buf^1); storeB(buf^1);
            __syncthreads();
            buf ^= 1;
        }
    }
#pragma unroll
    for (int i=0;i<TM;i++) {
        size_t m = (size_t)(m0 + ty*TM + i);
#pragma unroll
        for (int j4=0;j4<TN/4;j4++) {
            int n = n0 + tx*TN + j4*4;
            float4 v;
            v.x = acc[i][j4*4+0]*alpha; v.y = acc[i][j4*4+1]*alpha;
            v.z = acc[i][j4*4+2]*alpha; v.w = acc[i][j4*4+3]*alpha;
            if (bias) { v.x+=bias[n]; v.y+=bias[n+1]; v.z+=bias[n+2]; v.w+=bias[n+3]; }
            *(float4*)(Cp + m*ldc + n) = v;
        }
    }
}

// ---------------- channel self-attention core ----------------
__global__ __launch_bounds__(1024)
void self_attn_kernel(const float* __restrict__ Q, const float* __restrict__ Kx,
                      const float* __restrict__ V, float* __restrict__ O)
{
    __shared__ float qs[1024], ks[1024], vs[1024];
    size_t base = (size_t)blockIdx.x*1024;
    int tid = threadIdx.x;
    qs[tid] = Q[base+tid]*0.125f;
    ks[tid] = Kx[base+tid];
    vs[tid] = V[base+tid];
    __syncthreads();
    int q = tid & 63, hb = tid & ~63;
    float qv = qs[hb+q];
    float m = -1e30f;
    for (int k=0;k<=q;k++) m = fmaxf(m, qv*ks[hb+k]);
    float s=0.f, a=0.f;
    for (int k=0;k<=q;k++) {
        float e = __expf(qv*ks[hb+k]-m);
        s += e; a = fmaf(e, vs[hb+k], a);
    }
    O[base+tid] = a/s;
}

// ---------------- softmax over rows of 512 (warp per row) ----------------
__global__ __launch_bounds__(256)
void softmax512_kernel(float* __restrict__ P)
{
    int row  = blockIdx.x*8 + (threadIdx.x>>5);
    int lane = threadIdx.x & 31;
    float* r = P + (size_t)row*512;
    float v[16];
    float m = -1e30f;
#pragma unroll
    for (int i=0;i<16;i++) { v[i] = r[lane + i*32]; m = fmaxf(m, v[i]); }
#pragma unroll
    for (int o=16;o;o>>=1) m = fmaxf(m, __shfl_xor_sync(0xffffffffu, m, o));
    float s = 0.f;
#pragma unroll
    for (int i=0;i<16;i++) { v[i] = __expf(v[i]-m); s += v[i]; }
#pragma unroll
    for (int o=16;o;o>>=1) s += __shfl_xor_sync(0xffffffffu, s, o);
    float inv = 1.f/s;
#pragma unroll
    for (int i=0;i<16;i++) r[lane + i*32] = v[i]*inv;
}

// ---------------- residual add + LayerNorm ----------------
__global__ __launch_bounds__(256)
void add_ln_kernel(const float* __restrict__ a, const float* __restrict__ b,
                   const float* __restrict__ gamma, const float* __restrict__ beta,
                   float* __restrict__ out)
{
    __shared__ float s[1024];
    __shared__ float red[33];
    size_t base = (size_t)blockIdx.x*1024;
    int tid = threadIdx.x;
    float local = 0.f;
#pragma unroll
    for (int i=0;i<4;i++) {
        int idx = tid + i*256;
        float v = a[base+idx] + b[base+idx];
        s[idx] = v; local += v;
    }
    int lane = tid & 31, w = tid >> 5;
#pragma unroll
    for (int o=16;o;o>>=1) local += __shfl_xor_sync(0xffffffffu, local, o);
    if (lane==0) red[w] = local;
    __syncthreads();
    if (w==0) {
        float t = (lane<8)? red[lane] : 0.f;
#pragma unroll
        for (int o=16;o;o>>=1) t += __shfl_xor_sync(0xffffffffu, t, o);
        if (lane==0) red[32] = t * (1.f/1024.f);
    }
    __syncthreads();
    float mu = red[32];
    __syncthreads();
    float lv = 0.f;
#pragma unroll
    for (int i=0;i<4;i++) { float d = s[tid+i*256]-mu; lv = fmaf(d,d,lv); }
#pragma unroll
    for (int o=16;o;o>>=1) lv += __shfl_xor_sync(0xffffffffu, lv, o);
    if (lane==0) red[w] = lv;
    __syncthreads();
    if (w==0) {
        float t = (lane<8)? red[lane] : 0.f;
#pragma unroll
        for (int o=16;o;o>>=1) t += __shfl_xor_sync(0xffffffffu, t, o);
        if (lane==0) red[32] = rsqrtf(t*(1.f/1024.f) + 1e-5f);
    }
    __syncthreads();
    float rstd = red[32];
#pragma unroll
    for (int i=0;i<4;i++) {
        int idx = tid + i*256;
        out[base+idx] = (s[idx]-mu)*rstd*gamma[idx] + beta[idx];
    }
}

// ---------------- host-side wrappers ----------------
static __nv_bfloat16 *s_ah, *s_al, *s_wh, *s_wl;

static void actsplit(const float* x) {
    actsplit_kernel<<<(MT*DD/4)/256, 256>>>(x, s_ah, s_al);
}
static void tg(const float* W, const float* bias, float* C) {
    wsplit_kernel<<<dim3(HH/32, DD/32), 256>>>(W, s_wh, s_wl);
    tgemm_kernel<<<dim3(HH/128, MT/128), 256, MM_SMEM>>>(s_ah, s_al, s_wh, s_wl, bias, C);
}

extern "C" void kernel_launch(void* const* d_in, const int* in_sizes, int n_in,
                              void* d_out, int out_size)
{
    const float* x    = (const float*)d_in[0];
    const float* h    = (const float*)d_in[1];
    const float* Wq   = (const float*)d_in[2];
    const float* bq   = (const float*)d_in[3];
    const float* Wk   = (const float*)d_in[4];
    const float* bk   = (const float*)d_in[5];
    const float* Wv   = (const float*)d_in[6];
    const float* bv   = (const float*)d_in[7];
    const float* Wo   = (const float*)d_in[8];
    const float* bo   = (const float*)d_in[9];
    const float* Wcq  = (const float*)d_in[10];
    const float* bcq  = (const float*)d_in[11];
    const float* Wck  = (const float*)d_in[12];
    const float* bck  = (const float*)d_in[13];
    const float* Wcv  = (const float*)d_in[14];
    const float* bcv  = (const float*)d_in[15];
    const float* Wco  = (const float*)d_in[16];
    const float* bco  = (const float*)d_in[17];
    const float* gamma= (const float*)d_in[18];
    const float* beta = (const float*)d_in[19];
    const float* W1   = (const float*)d_in[20];
    const float* b1   = (const float*)d_in[21];
    const float* W2   = (const float*)d_in[22];
    const float* b2   = (const float*)d_in[23];
    float* out = (float*)d_out;

    static float *q=nullptr,*k,*v,*a,*t,*x1,*x2,*sc;
    if (!q) {
        cudaGetSymbolAddress((void**)&q,  g_q);
        cudaGetSymbolAddress((void**)&k,  g_k);
        cudaGetSymbolAddress((void**)&v,  g_v);
        cudaGetSymbolAddress((void**)&a,  g_a);
        cudaGetSymbolAddress((void**)&t,  g_t);
        cudaGetSymbolAddress((void**)&x1, g_x1);
        cudaGetSymbolAddress((void**)&x2, g_x2);
        cudaGetSymbolAddress((void**)&sc, g_sc);
        cudaGetSymbolAddress((void**)&s_ah, g_ah);
        cudaGetSymbolAddress((void**)&s_al, g_al);
        cudaGetSymbolAddress((void**)&s_wh, g_wh);
        cudaGetSymbolAddress((void**)&s_wl, g_wl);
        cudaFuncSetAttribute(tgemm_kernel,
                             cudaFuncAttributeMaxDynamicSharedMemorySize, MM_SMEM);
    }

    const long long sT = (long long)SS*HH;        // token-batch stride (per b)
    const long long sH = 64;                      // head stride inside HID
    const long long sSo = (long long)NHH*SS*SS;   // scores: per-b stride
    const long long sSi = (long long)SS*SS;       // scores: per-h stride

    // ---- self attention ----
    actsplit(x);
    tg(Wq, bq, q);
    tg(Wk, bk, k);
    tg(Wv, bv, v);
    self_attn_kernel<<<MT, 1024>>>(q, k, v, a);
    actsplit(a);
    tg(Wo, bo, t);
    add_ln_kernel<<<MT, 256>>>(t, x, gamma, beta, x1);

    // ---- cross attention ----
    actsplit(x1);
    tg(Wcq, bcq, q);
    actsplit(h);
    tg(Wck, bck, k);
    tg(Wcv, bcv, v);
    {   // scores = Q K^T / 32   (batched over B x NH)
        dim3 g(SS/64, SS/64, NBATCH);
        gemm_kernel<64,64,16,4,4,true><<<g,256>>>(SS,SS,CC,
            q, HH, sT, sH,
            k, HH, sT, sH,
            sc, SS, sSo, sSi,
            nullptr, 1.f/32.f, NHH);
    }
    softmax512_kernel<<<(NBATCH*SS)/8, 256>>>(sc);
    {   // O = P V  (writes directly into [B,S,HID] layout)
        dim3 g(CC/64, SS/64, NBATCH);
        gemm_kernel<64,64,16,4,4,false><<<g,256>>>(SS,CC,SS,
            sc, SS, sSo, sSi,
            v,  HH, sT, sH,
            a,  HH, sT, sH,
            nullptr, 1.f, NHH);
    }
    actsplit(a);
    tg(Wco, bco, t);
    add_ln_kernel<<<MT, 256>>>(t, x1, gamma, beta, x2);

    // ---- FFN (linear-linear) ----
    actsplit(x2);
    tg(W1, b1, q);
    actsplit(q);
    tg(W2, b2, t);
    add_ln_kernel<<<MT, 256>>>(t, x2, gamma, beta, out);
}